// round 9
// baseline (speedup 1.0000x reference)
#include <cuda_runtime.h>
#include <math.h>
#include <stdint.h>

#define BB   32
#define TT   512
#define HH   256
#define CC   32
#define G4   1024   // 4*H
#define DD   256

typedef unsigned long long ull;

// ---------------- scratch (no allocations allowed) ----------------
// gx layout: [dir][t][b][col]  (col fastest, 1024 per dir)
__device__ float g_gx[(size_t)2 * TT * BB * G4];     // 134 MB
__device__ float g_hist[(size_t)2 * TT * HH * BB];   // [dir][t][n][b]  33 MB
__device__ float g_logits[(size_t)TT * BB * CC];     // [t][b][c]        2 MB
// h exchange slabs: [dir][bg][parity][k*4 + bl]  (duplicated fp32x2 values)
__device__ ull   g_hx[2 * 8 * 2 * 1024];             // 256 KB
__device__ int   g_flag[2 * 8 * 8];                  // [dir][bg][cg]

// ---------------- packed fp32x2 helpers ----------------
__device__ __forceinline__ ull ffma2(ull a, ull b, ull c) {
    ull d;
    asm("fma.rn.f32x2 %0, %1, %2, %3;" : "=l"(d) : "l"(a), "l"(b), "l"(c));
    return d;
}
__device__ __forceinline__ ull padd2(ull a, ull b) {
    ull d;
    asm("add.rn.f32x2 %0, %1, %2;" : "=l"(d) : "l"(a), "l"(b));
    return d;
}
__device__ __forceinline__ ull dup2(float x) {
    ull p = (ull)__float_as_uint(x);
    return p | (p << 32);
}
__device__ __forceinline__ float2 unp(ull v) {
    float2 f;
    asm("mov.b64 {%0, %1}, %2;" : "=f"(f.x), "=f"(f.y) : "l"(v));
    return f;
}

__device__ __forceinline__ float sigf(float x)  { return __fdividef(1.f, 1.f + __expf(-x)); }
__device__ __forceinline__ float tanhf_(float x){ return __fdividef(2.f, 1.f + __expf(-2.f * x)) - 1.f; }

// ---------------- init: zero flags each replay ----------------
__global__ void init_kernel() {
    int i = blockIdx.x * blockDim.x + threadIdx.x;
    if (i < 2 * 8 * 8) g_flag[i] = 0;
}

// ---------------- kernel A: embedding gather + x@Wi + bias (fp32x2) ----------------
// grid (512, 16): x = t, y = dir*8 + colblock(128 cols). 256 threads.
// smem: a_sm [256][32] floats (32KB, reused for transpose) + wd_sm [64][128] ull dup (64KB)
__global__ void __launch_bounds__(256) wi_gemm_kernel(
        const int* __restrict__ chars,
        const int* __restrict__ bigrams,
        const float* __restrict__ char_table,
        const float* __restrict__ bigram_table,
        const float* __restrict__ Wi_f,
        const float* __restrict__ bias_f,
        const float* __restrict__ Wi_b,
        const float* __restrict__ bias_b) {
    extern __shared__ float sm[];
    float* a_sm = sm;                       // 8192 floats = 32KB
    ull*   wd_sm = (ull*)(sm + 8192);       // 8192 ull = 64KB

    const int t   = blockIdx.x;
    const int yid = blockIdx.y;
    const int dir = yid >> 3;
    const int cb  = yid & 7;
    const float* Wi   = dir ? Wi_b  : Wi_f;
    const float* bias = dir ? bias_b : bias_f;

    const int tid = threadIdx.x;

    // ---- gather emb -> a_sm[k][b]  (lane = b -> conflict-free STS) ----
    {
        const int b    = tid & 31;
        const int part = tid >> 5;   // 0..7
        const int ci = chars[b * TT + t];
        const int bi = bigrams[b * TT + t];
        #pragma unroll
        for (int i = 0; i < 8; i++) {
            int k4 = part * 8 + i;   // 0..63
            float4 v;
            if (k4 < 32) v = ((const float4*)char_table)[(size_t)ci * 32 + k4];
            else         v = ((const float4*)bigram_table)[(size_t)bi * 32 + (k4 - 32)];
            a_sm[(k4 * 4 + 0) * 32 + b] = v.x;
            a_sm[(k4 * 4 + 1) * 32 + b] = v.y;
            a_sm[(k4 * 4 + 2) * 32 + b] = v.z;
            a_sm[(k4 * 4 + 3) * 32 + b] = v.w;
        }
    }

    // ---- GEMM mapping: thread = (4 cols, 4 batches) ----
    const int cg = tid >> 3;   // 0..31 : cols cg*4 .. cg*4+3
    const int bq = tid & 7;    // batches 4bq .. 4bq+3
    ull acc[8];
    #pragma unroll
    for (int i = 0; i < 8; i++) acc[i] = 0ull;

    const ulonglong2* a2 = (const ulonglong2*)a_sm;

    for (int ch = 0; ch < 4; ch++) {
        const int k0 = ch * 64;
        __syncthreads();
        for (int u = tid; u < 8192; u += 256) {
            int kk  = u >> 7;
            int col = u & 127;
            float wv = Wi[(size_t)(k0 + kk) * G4 + cb * 128 + col];
            wd_sm[u] = dup2(wv);
        }
        __syncthreads();
        #pragma unroll 8
        for (int kk = 0; kk < 64; kk++) {
            ulonglong2 hv = a2[(k0 + kk) * 8 + bq];   // 4 batches: (b0,b1),(b2,b3)
            const ull* wr = &wd_sm[kk * 128 + cg * 4];
            #pragma unroll
            for (int c = 0; c < 4; c++) {
                ull wd = wr[c];
                acc[2 * c]     = ffma2(hv.x, wd, acc[2 * c]);
                acc[2 * c + 1] = ffma2(hv.y, wd, acc[2 * c + 1]);
            }
        }
    }

    // ---- transpose in smem, then store as [dir][t][b][col] ----
    __syncthreads();
    {
        #pragma unroll
        for (int cc = 0; cc < 4; cc++) {
            int col = cg * 4 + cc;
            ull b2 = dup2(bias[cb * 128 + col]);
            float2 v01 = unp(padd2(acc[2 * cc],     b2));
            float2 v23 = unp(padd2(acc[2 * cc + 1], b2));
            a_sm[(bq * 4 + 0) * 129 + col] = v01.x;
            a_sm[(bq * 4 + 1) * 129 + col] = v01.y;
            a_sm[(bq * 4 + 2) * 129 + col] = v23.x;
            a_sm[(bq * 4 + 3) * 129 + col] = v23.y;
        }
    }
    __syncthreads();
    {
        float* outp = g_gx + (size_t)(dir * TT + t) * (32 * 1024) + cb * 128;
        #pragma unroll
        for (int i = 0; i < 4; i++) {
            int idx = tid + i * 256;      // 0..1023
            int b = idx >> 5, c4 = idx & 31;
            float4 v;
            v.x = a_sm[b * 129 + c4 * 4 + 0];
            v.y = a_sm[b * 129 + c4 * 4 + 1];
            v.z = a_sm[b * 129 + c4 * 4 + 2];
            v.w = a_sm[b * 129 + c4 * 4 + 3];
            *(float4*)(outp + (size_t)b * 1024 + c4 * 4) = v;
        }
    }
}

// ---------------- kernel B: recurrent scan, L2 data+flag handshake ----------------
// grid 128 CTAs of 128 threads: (dir, batch-group of 4, col-group of 32 h-cols).
// Only the 8 col-group CTAs of one (dir,bg) synchronize, via gmem slab + flags.
// smem: Wh slice [256][128] f32 (128KB) | hd [256][4] ull dup (8KB) | gates [128][4] (2KB) | hout [128] (0.5KB)
__global__ void __launch_bounds__(128, 1)
scan_kernel(const float* __restrict__ Wh_f,
            const float* __restrict__ Wh_b,
            const int* __restrict__ seq_len) {
    extern __shared__ float sm[];
    float* sm_wh = sm;                      // 32768 floats
    ull*   sm_hd = (ull*)(sm + 32768);      // 1024 ull
    float* sm_g  = (float*)(sm_hd + 1024);  // 512 floats
    float* sm_ho = sm_g + 512;              // 128 floats

    const int cta = blockIdx.x;
    const int dir = cta >> 6;
    const int bg  = (cta >> 3) & 7;
    const int cg  = cta & 7;
    const float* Wh = dir ? Wh_b : Wh_f;
    const int tid = threadIdx.x;

    // load Wh slice: sm_wh[k*128 + g*32 + m] = Wh[k][g*256 + cg*32 + m]
    {
        const float4* W4 = (const float4*)Wh;
        float4* d4 = (float4*)sm_wh;
        for (int u = tid; u < 8192; u += 128) {
            int k = u >> 5, l4 = u & 31;
            d4[u] = W4[(k * 1024 + (l4 >> 3) * 256 + cg * 32 + (l4 & 7) * 4) >> 2];
        }
    }

    // GEMM-phase mapping: thread = (col pair l0=2jp,l0+1) x (2 batches)
    const int jp = tid >> 1;                 // 0..63
    const int bh = tid & 1;                  // 0..1
    // combine-phase mapping
    const int m  = tid & 31;                 // h col within group
    const int bl = tid >> 5;                 // 0..3 local batch
    const int b_glob = bg * 4 + bl;
    const int sl = seq_len[b_glob];
    const int ncol = cg * 32 + m;            // global h col

    const int gq  = jp >> 4;                               // gate index of l0
    const int c0g = gq * 256 + cg * 32 + ((2 * jp) & 31);  // global gate col of l0
    const int b0  = bg * 4 + 2 * bh;

    volatile int* flg = (volatile int*)&g_flag[(dir * 8 + bg) * 8];
    ull* slab = &g_hx[(size_t)((dir * 8 + bg) * 2) * 1024];

    float c_reg = 0.f, h_prev = 0.f;

    // prefetch gx for first step
    int t0 = dir ? (TT - 1) : 0;
    size_t gidx = ((size_t)(dir * TT + t0) * 32 + b0) * 1024 + c0g;
    ull gx0 = *(const ull*)(g_gx + gidx);
    ull gx1 = *(const ull*)(g_gx + gidx + 1024);

    for (int p = 0; p < TT; p++) {
        const int t = dir ? (TT - 1 - p) : p;

        // acquire previous h
        if (p == 0) {
            for (int u = tid; u < 1024; u += 128) sm_hd[u] = 0ull;
        } else {
            // wait for all 8 CTAs to have published step p-1
            for (;;) {
                int ok = 1;
                #pragma unroll
                for (int r = 0; r < 8; r++) ok &= (flg[r] >= p);
                if (ok) break;
            }
            __threadfence();
            const ulonglong2* src = (const ulonglong2*)(slab + ((p - 1) & 1) * 1024);
            ulonglong2* dst = (ulonglong2*)sm_hd;
            #pragma unroll
            for (int i = 0; i < 4; i++) dst[tid + i * 128] = src[tid + i * 128];
        }
        __syncthreads();

        // gates = gx + h @ Wh (packed fp32x2)
        ull a0 = gx0, a1 = gx1;
        #pragma unroll 8
        for (int k = 0; k < 256; k++) {
            ulonglong2 hv = ((const ulonglong2*)sm_hd)[k * 2 + bh]; // {b0,b0},{b1,b1}
            ull wv = *(const ull*)&sm_wh[k * 128 + 2 * jp];         // {w_l0, w_l1}
            a0 = ffma2(wv, hv.x, a0);
            a1 = ffma2(wv, hv.y, a1);
        }

        // prefetch next step's gx (latency hidden behind gate staging/combine)
        if (p < TT - 1) {
            int tn = dir ? (t - 1) : (t + 1);
            size_t gi = ((size_t)(dir * TT + tn) * 32 + b0) * 1024 + c0g;
            gx0 = *(const ull*)(g_gx + gi);
            gx1 = *(const ull*)(g_gx + gi + 1024);
        }

        // stage gates: sm_g[l*4 + b]
        {
            float2 f0 = unp(a0), f1 = unp(a1);
            int l0 = 2 * jp;
            sm_g[ l0      * 4 + 2 * bh    ] = f0.x;
            sm_g[(l0 + 1) * 4 + 2 * bh    ] = f0.y;
            sm_g[ l0      * 4 + 2 * bh + 1] = f1.x;
            sm_g[(l0 + 1) * 4 + 2 * bh + 1] = f1.y;
        }
        __syncthreads();

        // combine: thread = (h col m, batch bl)
        float gi_ = sm_g[( 0 + m) * 4 + bl];
        float gf_ = sm_g[(32 + m) * 4 + bl];
        float gc_ = sm_g[(64 + m) * 4 + bl];
        float go_ = sm_g[(96 + m) * 4 + bl];
        float c_new = sigf(gf_) * c_reg + sigf(gi_) * tanhf_(gc_);
        float h_new = sigf(go_) * tanhf_(c_new);
        bool  msk = (t < sl);
        if (msk) c_reg = c_new;
        float h_out = msk ? h_new : h_prev;
        h_prev = h_out;

        // publish h for peers (duplicated) + stage for coalesced g_hist store
        if (p < TT - 1)
            slab[(p & 1) * 1024 + ncol * 4 + bl] = dup2(h_out);
        sm_ho[m * 4 + bl] = h_out;
        __threadfence();
        __syncthreads();

        // coalesced g_hist store: [n][b] 16B chunks
        if (tid < 32) {
            float4 v = *(const float4*)&sm_ho[tid * 4];
            *(float4*)&g_hist[((size_t)(dir * TT + t) * HH + cg * 32 + tid) * BB + bg * 4] = v;
        }

        if (p < TT - 1 && tid == 0) flg[cg] = p + 1;
        __syncthreads();   // protect sm_ho/sm_g reuse next iteration
    }
}

// ---------------- kernel C: output projection + log_softmax ----------------
// grid 512 (t), 256 threads. smem: hsm[512][32] + lsm[32][33] + lse[32]  (~70KB -> 3 CTAs/SM)
__global__ void proj_kernel(const float* __restrict__ out_W,
                            const float* __restrict__ out_b) {
    extern __shared__ float sm[];
    float* hsm = sm;                       // 512*32
    float* lsm = sm + 512 * 32;            // 32*33
    float* lse = lsm + 32 * 33;            // 32

    const int t   = blockIdx.x;
    const int tid = threadIdx.x;

    float4* hd = (float4*)hsm;
    const float4* h0 = (const float4*)(g_hist + (size_t)t * HH * BB);
    const float4* h1 = (const float4*)(g_hist + (size_t)(TT + t) * HH * BB);
    #pragma unroll
    for (int i = 0; i < 16; i++) {
        int idx = tid + i * 256;           // 0..4095 float4
        hd[idx] = (idx < 2048) ? h0[idx] : h1[idx - 2048];
    }
    __syncthreads();

    const int b  = tid & 31;
    const int cg = tid >> 5;
    float acc[4];
    #pragma unroll
    for (int jj = 0; jj < 4; jj++) acc[jj] = out_b[cg * 4 + jj];
    #pragma unroll 8
    for (int k = 0; k < 512; k++) {
        float  hv = hsm[k * 32 + b];
        float4 ww = __ldg((const float4*)&out_W[k * CC + cg * 4]);  // warp-uniform, cached
        acc[0] += hv * ww.x; acc[1] += hv * ww.y; acc[2] += hv * ww.z; acc[3] += hv * ww.w;
    }
    #pragma unroll
    for (int jj = 0; jj < 4; jj++) lsm[b * 33 + cg * 4 + jj] = acc[jj];
    __syncthreads();

    if (tid < 32) {
        float mx = -1e30f;
        #pragma unroll
        for (int c = 0; c < 32; c++) mx = fmaxf(mx, lsm[tid * 33 + c]);
        float ssum = 0.f;
        #pragma unroll
        for (int c = 0; c < 32; c++) ssum += expf(lsm[tid * 33 + c] - mx);
        lse[tid] = mx + logf(ssum);
    }
    __syncthreads();

    float l = lse[b];
    #pragma unroll
    for (int jj = 0; jj < 4; jj++)
        g_logits[(size_t)t * BB * CC + b * CC + cg * 4 + jj] = acc[jj] - l;
}

// ---------------- kernel D: CRF normalizer + gold score (4 warps/batch) ----------------
// grid 32 (b), 128 threads. Warp w handles predecessors i in [8w, 8w+8).
// alpha replicated across warps (lane j holds alpha_j in every warp).
__global__ void __launch_bounds__(128) crf_kernel(
        const int* __restrict__ seq_len,
        const int* __restrict__ target,
        const float* __restrict__ trans,
        const float* __restrict__ start_trans,
        const float* __restrict__ end_trans,
        float* __restrict__ out) {
    __shared__ float sm_m[2][4][32];
    __shared__ float sm_s[2][4][32];
    __shared__ float sm_r[4];

    const int b   = blockIdx.x;
    const int tid = threadIdx.x;
    const int j   = tid & 31;
    const int w   = tid >> 5;
    const int sl  = seq_len[b];

    // this warp's slice of the transition matrix: tr8[ii] = trans[8w+ii][j]
    float tr8[8];
    #pragma unroll
    for (int ii = 0; ii < 8; ii++) tr8[ii] = trans[(8 * w + ii) * 32 + j];

    float alpha = g_logits[(size_t)b * CC + j] + start_trans[j];

    for (int t = 1; t < sl; t++) {
        float emit = g_logits[(size_t)t * BB * CC + b * CC + j];

        // partial LSE over this warp's 8 predecessors
        float v[8];
        #pragma unroll
        for (int ii = 0; ii < 8; ii++)
            v[ii] = __shfl_sync(0xffffffffu, alpha, 8 * w + ii) + tr8[ii];
        float mw = fmaxf(fmaxf(fmaxf(v[0], v[1]), fmaxf(v[2], v[3])),
                         fmaxf(fmaxf(v[4], v[5]), fmaxf(v[6], v[7])));
        float sw = 0.f;
        #pragma unroll
        for (int ii = 0; ii < 8; ii++) sw += __expf(v[ii] - mw);

        int par = t & 1;
        sm_m[par][w][j] = mw;
        sm_s[par][w][j] = sw;
        __syncthreads();

        // combine 4 partials (every warp computes identically -> alpha stays replicated)
        float m0 = sm_m[par][0][j], m1 = sm_m[par][1][j];
        float m2 = sm_m[par][2][j], m3 = sm_m[par][3][j];
        float M = fmaxf(fmaxf(m0, m1), fmaxf(m2, m3));
        float S = sm_s[par][0][j] * __expf(m0 - M) + sm_s[par][1][j] * __expf(m1 - M)
                + sm_s[par][2][j] * __expf(m2 - M) + sm_s[par][3][j] * __expf(m3 - M);
        alpha = M + __logf(S) + emit;
    }

    // normalizer = LSE_j(alpha + end_trans)  (replicated; use warp 0 at the end)
    float vv = alpha + end_trans[j];
    float mx = vv;
    #pragma unroll
    for (int o = 16; o > 0; o >>= 1) mx = fmaxf(mx, __shfl_xor_sync(0xffffffffu, mx, o));
    float se = __expf(vv - mx);
    #pragma unroll
    for (int o = 16; o > 0; o >>= 1) se += __shfl_xor_sync(0xffffffffu, se, o);
    float norm = mx + logf(se);

    // gold path score: threads strided over t
    float gs = 0.f;
    for (int t = tid; t < sl; t += 128) {
        int tg = target[b * TT + t];
        gs += g_logits[(size_t)t * BB * CC + b * CC + tg];
        if (t >= 1) gs += trans[target[b * TT + t - 1] * 32 + tg];
    }
    #pragma unroll
    for (int o = 16; o > 0; o >>= 1) gs += __shfl_xor_sync(0xffffffffu, gs, o);
    if (j == 0) sm_r[w] = gs;
    __syncthreads();

    if (tid == 0) {
        float g = sm_r[0] + sm_r[1] + sm_r[2] + sm_r[3]
                + start_trans[target[b * TT]] + end_trans[target[b * TT + sl - 1]];
        out[b] = norm - g;
    }
}

// ---------------- launch ----------------
extern "C" void kernel_launch(void* const* d_in, const int* in_sizes, int n_in,
                              void* d_out, int out_size) {
    const int*   chars        = (const int*)d_in[0];
    const int*   bigrams      = (const int*)d_in[1];
    const int*   seq_len      = (const int*)d_in[2];
    const int*   target       = (const int*)d_in[3];
    const float* char_table   = (const float*)d_in[4];
    const float* bigram_table = (const float*)d_in[5];
    const float* Wi_f         = (const float*)d_in[6];
    const float* Wh_f         = (const float*)d_in[7];
    const float* b_f          = (const float*)d_in[8];
    const float* Wi_b         = (const float*)d_in[9];
    const float* Wh_b         = (const float*)d_in[10];
    const float* b_b          = (const float*)d_in[11];
    const float* out_W        = (const float*)d_in[12];
    const float* out_b        = (const float*)d_in[13];
    const float* trans        = (const float*)d_in[14];
    const float* start_trans  = (const float*)d_in[15];
    const float* end_trans    = (const float*)d_in[16];
    float* out = (float*)d_out;

    const int SMEM_A = 32768 + 65536;                                   // 98304
    const int SMEM_S = 32768 * 4 + 1024 * 8 + 512 * 4 + 128 * 4;        // 141824
    const int SMEM_P = (512 * 32 + 32 * 33 + 32) * (int)sizeof(float);  // 69888

    cudaFuncSetAttribute(wi_gemm_kernel, cudaFuncAttributeMaxDynamicSharedMemorySize, SMEM_A);
    cudaFuncSetAttribute(scan_kernel,    cudaFuncAttributeMaxDynamicSharedMemorySize, SMEM_S);
    cudaFuncSetAttribute(proj_kernel,    cudaFuncAttributeMaxDynamicSharedMemorySize, SMEM_P);

    init_kernel<<<1, 128>>>();

    dim3 ga(TT, 16);
    wi_gemm_kernel<<<ga, 256, SMEM_A>>>(chars, bigrams, char_table, bigram_table,
                                        Wi_f, b_f, Wi_b, b_b);

    scan_kernel<<<128, 128, SMEM_S>>>(Wh_f, Wh_b, seq_len);

    proj_kernel<<<TT, 256, SMEM_P>>>(out_W, out_b);

    crf_kernel<<<BB, 128>>>(seq_len, target, trans, start_trans, end_trans, out);
}

// round 10
// speedup vs baseline: 2.1569x; 2.1569x over previous
#include <cuda_runtime.h>
#include <math.h>
#include <stdint.h>

#define BB   32
#define TT   512
#define HH   256
#define CC   32
#define G4   1024   // 4*H
#define DD   256

typedef unsigned long long ull;

// ---------------- scratch (no allocations allowed) ----------------
// gx layout: [dir][t][b][col]  (col fastest, 1024 per dir)
__device__ float g_gx[(size_t)2 * TT * BB * G4];     // 134 MB
__device__ float g_hist[(size_t)2 * TT * HH * BB];   // [dir][t][n][b]  33 MB
__device__ float g_logits[(size_t)TT * BB * CC];     // [t][b][c]        2 MB
// h exchange slabs per group: [16][parity][256 cols][4 b] duplicated ull
__device__ ull   g_hx[16 * 2048];                    // 256 KB
__device__ int   g_ctr[16 * 32];                     // 1 counter per group, 128B apart

// ---------------- packed fp32x2 helpers ----------------
__device__ __forceinline__ ull ffma2(ull a, ull b, ull c) {
    ull d;
    asm("fma.rn.f32x2 %0, %1, %2, %3;" : "=l"(d) : "l"(a), "l"(b), "l"(c));
    return d;
}
__device__ __forceinline__ ull padd2(ull a, ull b) {
    ull d;
    asm("add.rn.f32x2 %0, %1, %2;" : "=l"(d) : "l"(a), "l"(b));
    return d;
}
__device__ __forceinline__ ull dup2(float x) {
    ull p = (ull)__float_as_uint(x);
    return p | (p << 32);
}
__device__ __forceinline__ float2 unp(ull v) {
    float2 f;
    asm("mov.b64 {%0, %1}, %2;" : "=f"(f.x), "=f"(f.y) : "l"(v));
    return f;
}

__device__ __forceinline__ float sigf(float x)  { return __fdividef(1.f, 1.f + __expf(-x)); }
__device__ __forceinline__ float tanhf_(float x){ return __fdividef(2.f, 1.f + __expf(-2.f * x)) - 1.f; }

// ---------------- init: zero counters each replay ----------------
__global__ void init_kernel() {
    int i = blockIdx.x * blockDim.x + threadIdx.x;
    if (i < 16 * 32) g_ctr[i] = 0;
}

// ---------------- kernel A: embedding gather + x@Wi + bias (fp32x2) ----------------
// grid (512, 16): x = t, y = dir*8 + colblock(128 cols). 256 threads.
__global__ void __launch_bounds__(256) wi_gemm_kernel(
        const int* __restrict__ chars,
        const int* __restrict__ bigrams,
        const float* __restrict__ char_table,
        const float* __restrict__ bigram_table,
        const float* __restrict__ Wi_f,
        const float* __restrict__ bias_f,
        const float* __restrict__ Wi_b,
        const float* __restrict__ bias_b) {
    extern __shared__ float sm[];
    float* a_sm = sm;                       // 8192 floats = 32KB
    ull*   wd_sm = (ull*)(sm + 8192);       // 8192 ull = 64KB

    const int t   = blockIdx.x;
    const int yid = blockIdx.y;
    const int dir = yid >> 3;
    const int cb  = yid & 7;
    const float* Wi   = dir ? Wi_b  : Wi_f;
    const float* bias = dir ? bias_b : bias_f;

    const int tid = threadIdx.x;

    // gather emb -> a_sm[k][b]
    {
        const int b    = tid & 31;
        const int part = tid >> 5;
        const int ci = chars[b * TT + t];
        const int bi = bigrams[b * TT + t];
        #pragma unroll
        for (int i = 0; i < 8; i++) {
            int k4 = part * 8 + i;
            float4 v;
            if (k4 < 32) v = ((const float4*)char_table)[(size_t)ci * 32 + k4];
            else         v = ((const float4*)bigram_table)[(size_t)bi * 32 + (k4 - 32)];
            a_sm[(k4 * 4 + 0) * 32 + b] = v.x;
            a_sm[(k4 * 4 + 1) * 32 + b] = v.y;
            a_sm[(k4 * 4 + 2) * 32 + b] = v.z;
            a_sm[(k4 * 4 + 3) * 32 + b] = v.w;
        }
    }

    const int cg = tid >> 3;   // cols cg*4 .. cg*4+3
    const int bq = tid & 7;    // batches 4bq .. 4bq+3
    ull acc[8];
    #pragma unroll
    for (int i = 0; i < 8; i++) acc[i] = 0ull;

    const ulonglong2* a2 = (const ulonglong2*)a_sm;

    for (int ch = 0; ch < 4; ch++) {
        const int k0 = ch * 64;
        __syncthreads();
        for (int u = tid; u < 8192; u += 256) {
            int kk  = u >> 7;
            int col = u & 127;
            float wv = Wi[(size_t)(k0 + kk) * G4 + cb * 128 + col];
            wd_sm[u] = dup2(wv);
        }
        __syncthreads();
        #pragma unroll 8
        for (int kk = 0; kk < 64; kk++) {
            ulonglong2 hv = a2[(k0 + kk) * 8 + bq];
            const ull* wr = &wd_sm[kk * 128 + cg * 4];
            #pragma unroll
            for (int c = 0; c < 4; c++) {
                ull wd = wr[c];
                acc[2 * c]     = ffma2(hv.x, wd, acc[2 * c]);
                acc[2 * c + 1] = ffma2(hv.y, wd, acc[2 * c + 1]);
            }
        }
    }

    // transpose in smem, then store as [dir][t][b][col]
    __syncthreads();
    {
        #pragma unroll
        for (int cc = 0; cc < 4; cc++) {
            int col = cg * 4 + cc;
            ull b2 = dup2(bias[cb * 128 + col]);
            float2 v01 = unp(padd2(acc[2 * cc],     b2));
            float2 v23 = unp(padd2(acc[2 * cc + 1], b2));
            a_sm[(bq * 4 + 0) * 129 + col] = v01.x;
            a_sm[(bq * 4 + 1) * 129 + col] = v01.y;
            a_sm[(bq * 4 + 2) * 129 + col] = v23.x;
            a_sm[(bq * 4 + 3) * 129 + col] = v23.y;
        }
    }
    __syncthreads();
    {
        float* outp = g_gx + (size_t)(dir * TT + t) * (32 * 1024) + cb * 128;
        #pragma unroll
        for (int i = 0; i < 4; i++) {
            int idx = tid + i * 256;
            int b = idx >> 5, c4 = idx & 31;
            float4 v;
            v.x = a_sm[b * 129 + c4 * 4 + 0];
            v.y = a_sm[b * 129 + c4 * 4 + 1];
            v.z = a_sm[b * 129 + c4 * 4 + 2];
            v.w = a_sm[b * 129 + c4 * 4 + 3];
            *(float4*)(outp + (size_t)b * 1024 + c4 * 4) = v;
        }
    }
}

// ---------------- kernel B: recurrent scan, 8-CTA groups, R5-style sync ----------------
// grid 128 CTAs of 128 threads: CTA = (dir, bg in 0..7, cg in 0..7).
// Group (dir,bg) = 8 CTAs exchanging h of 4 batches via L2 slab + 1 atomic counter.
// GEMM thread mapping: (j8 0..15: 8 cols, bh 0..1: 2 batches, kh 0..3: 64 k each).
__global__ void __launch_bounds__(128, 1)
scan_kernel(const float* __restrict__ Wh_f,
            const float* __restrict__ Wh_b,
            const int* __restrict__ seq_len) {
    extern __shared__ float sm[];
    float*      sm_wh   = sm;                             // [256][128] f32 = 128KB
    ull*        sm_hd   = (ull*)(sm + 32768);             // [256][4] dup ull = 8KB
    float*      sm_g    = (float*)(sm_hd + 1024);         // [4 b][128 l] = 2KB
    ulonglong2* sm_part = (ulonglong2*)(sm_g + 512);      // [3][32][4] u2 = 6KB
    float*      sm_ho   = (float*)(sm_part + 3 * 32 * 4); // [32][4] = 0.5KB

    const int cta = blockIdx.x;
    const int dir = cta >> 6;
    const int bg  = (cta >> 3) & 7;
    const int cg  = cta & 7;
    const float* Wh = dir ? Wh_b : Wh_f;
    const int tid = threadIdx.x;

    // load Wh slice: sm_wh[k*128 + g*32 + m] = Wh[k][g*256 + cg*32 + m]
    {
        const float4* W4 = (const float4*)Wh;
        float4* d4 = (float4*)sm_wh;
        for (int u = tid; u < 8192; u += 128) {
            int k = u >> 5, l4 = u & 31;
            d4[u] = W4[(k * 1024 + (l4 >> 3) * 256 + cg * 32 + (l4 & 7) * 4) >> 2];
        }
    }
    for (int u = tid; u < 1024; u += 128) sm_hd[u] = 0ull;

    // GEMM mapping
    const int j8 = tid & 15;          // col oct: local cols 8*j8 .. 8*j8+7
    const int bh = (tid >> 4) & 1;    // local batches 2bh, 2bh+1
    const int kh = tid >> 5;          // k quarter
    const int kbase = kh * 64;
    // combine mapping
    const int m  = tid & 31;
    const int bl = tid >> 5;
    const int b_glob = bg * 4 + bl;
    const int sl = seq_len[b_glob];
    const int ncol = cg * 32 + m;

    const int gq  = j8 >> 2;                               // gate of this col oct
    const int c0g = gq * 256 + cg * 32 + ((8 * j8) & 31);  // global gate col base
    const int b0  = bg * 4 + 2 * bh;

    int* ctrp = &g_ctr[(dir * 8 + bg) * 32];
    ull* slab = &g_hx[(size_t)(dir * 8 + bg) * 2048];

    float c_reg = 0.f, h_prev = 0.f;

    // prefetch gx for first step (kh==0 threads own the gx-carry)
    ulonglong2 q00, q01, q10, q11;
    {
        int t0 = dir ? (TT - 1) : 0;
        if (kh == 0) {
            size_t base = ((size_t)(dir * TT + t0) * 32 + b0) * 1024 + c0g;
            q00 = *(const ulonglong2*)(g_gx + base);
            q01 = *(const ulonglong2*)(g_gx + base + 4);
            q10 = *(const ulonglong2*)(g_gx + base + 1024);
            q11 = *(const ulonglong2*)(g_gx + base + 1028);
        }
    }
    __syncthreads();

    for (int p = 0; p < TT; p++) {
        const int t = dir ? (TT - 1 - p) : p;

        // acquire previous h (stage slab -> smem), R5-proven sync pattern
        if (p > 0) {
            if (tid == 0) {
                volatile int* vp = ctrp;
                while (*vp < 8 * p) { }
                __threadfence();
            }
            __syncthreads();
            const ulonglong2* src = (const ulonglong2*)(slab + ((p - 1) & 1) * 1024);
            ulonglong2* dst = (ulonglong2*)sm_hd;
            #pragma unroll
            for (int i = 0; i < 4; i++) dst[tid + i * 128] = src[tid + i * 128];
            __syncthreads();
        }

        // ---- GEMM: 8 cols x 2 batches x 64 k per thread ----
        ull a0, a1, a2, a3, a4, a5, a6, a7;
        if (kh == 0) {
            a0 = q00.x; a2 = q00.y; a4 = q01.x; a6 = q01.y;   // batch b0
            a1 = q10.x; a3 = q10.y; a5 = q11.x; a7 = q11.y;   // batch b0+1
        } else {
            a0 = a1 = a2 = a3 = a4 = a5 = a6 = a7 = 0ull;
        }
        #pragma unroll 8
        for (int kk = 0; kk < 64; kk++) {
            int k = kbase + kk;
            ulonglong2 w01 = *(const ulonglong2*)&sm_wh[k * 128 + 8 * j8];
            ulonglong2 w23 = *(const ulonglong2*)&sm_wh[k * 128 + 8 * j8 + 4];
            ulonglong2 hq  = *(const ulonglong2*)&sm_hd[k * 4 + 2 * bh];
            a0 = ffma2(w01.x, hq.x, a0);  a1 = ffma2(w01.x, hq.y, a1);
            a2 = ffma2(w01.y, hq.x, a2);  a3 = ffma2(w01.y, hq.y, a3);
            a4 = ffma2(w23.x, hq.x, a4);  a5 = ffma2(w23.x, hq.y, a5);
            a6 = ffma2(w23.y, hq.x, a6);  a7 = ffma2(w23.y, hq.y, a7);
        }

        // prefetch next step's gx (hidden behind reduction/combine)
        if (kh == 0 && p < TT - 1) {
            int tn = dir ? (t - 1) : (t + 1);
            size_t base = ((size_t)(dir * TT + tn) * 32 + b0) * 1024 + c0g;
            q00 = *(const ulonglong2*)(g_gx + base);
            q01 = *(const ulonglong2*)(g_gx + base + 4);
            q10 = *(const ulonglong2*)(g_gx + base + 1024);
            q11 = *(const ulonglong2*)(g_gx + base + 1028);
        }

        // ---- tree reduction over kh ----
        int slot = (bh * 16 + j8) * 4;
        if (kh & 1) {   // kh 1 -> slot block 0, kh 3 -> slot block 1
            ulonglong2* d = &sm_part[(kh >> 1) * 128 + slot];
            d[0] = make_ulonglong2(a0, a1); d[1] = make_ulonglong2(a2, a3);
            d[2] = make_ulonglong2(a4, a5); d[3] = make_ulonglong2(a6, a7);
        }
        __syncthreads();
        if (!(kh & 1)) {
            const ulonglong2* s = &sm_part[(kh >> 1) * 128 + slot];
            ulonglong2 r0 = s[0], r1 = s[1], r2 = s[2], r3 = s[3];
            a0 = padd2(a0, r0.x); a1 = padd2(a1, r0.y);
            a2 = padd2(a2, r1.x); a3 = padd2(a3, r1.y);
            a4 = padd2(a4, r2.x); a5 = padd2(a5, r2.y);
            a6 = padd2(a6, r3.x); a7 = padd2(a7, r3.y);
            if (kh == 2) {
                ulonglong2* d = &sm_part[2 * 128 + slot];
                d[0] = make_ulonglong2(a0, a1); d[1] = make_ulonglong2(a2, a3);
                d[2] = make_ulonglong2(a4, a5); d[3] = make_ulonglong2(a6, a7);
            }
        }
        __syncthreads();
        if (kh == 0) {
            const ulonglong2* s = &sm_part[2 * 128 + slot];
            ulonglong2 r0 = s[0], r1 = s[1], r2 = s[2], r3 = s[3];
            a0 = padd2(a0, r0.x); a1 = padd2(a1, r0.y);
            a2 = padd2(a2, r1.x); a3 = padd2(a3, r1.y);
            a4 = padd2(a4, r2.x); a5 = padd2(a5, r2.y);
            a6 = padd2(a6, r3.x); a7 = padd2(a7, r3.y);
            // write gates: sm_g[b_local][l]  (float4 per 4 cols)
            float2 f0 = unp(a0), f2 = unp(a2), f4 = unp(a4), f6 = unp(a6);
            float2 f1 = unp(a1), f3 = unp(a3), f5 = unp(a5), f7 = unp(a7);
            int lbase = 8 * j8;
            *(float4*)&sm_g[(2 * bh)     * 128 + lbase]     = make_float4(f0.x, f0.y, f2.x, f2.y);
            *(float4*)&sm_g[(2 * bh)     * 128 + lbase + 4] = make_float4(f4.x, f4.y, f6.x, f6.y);
            *(float4*)&sm_g[(2 * bh + 1) * 128 + lbase]     = make_float4(f1.x, f1.y, f3.x, f3.y);
            *(float4*)&sm_g[(2 * bh + 1) * 128 + lbase + 4] = make_float4(f5.x, f5.y, f7.x, f7.y);
        }
        __syncthreads();

        // ---- combine: thread = (h col m, batch bl) ----
        float gi_ = sm_g[bl * 128 +  0 + m];
        float gf_ = sm_g[bl * 128 + 32 + m];
        float gc_ = sm_g[bl * 128 + 64 + m];
        float go_ = sm_g[bl * 128 + 96 + m];
        float c_new = sigf(gf_) * c_reg + sigf(gi_) * tanhf_(gc_);
        float h_new = sigf(go_) * tanhf_(c_new);
        bool  msk = (t < sl);
        if (msk) c_reg = c_new;
        float h_out = msk ? h_new : h_prev;
        h_prev = h_out;

        // publish for peers + stage for coalesced hist store
        if (p < TT - 1)
            slab[(p & 1) * 1024 + ncol * 4 + bl] = dup2(h_out);
        sm_ho[m * 4 + bl] = h_out;
        __threadfence();
        __syncthreads();

        if (tid == 0 && p < TT - 1) atomicAdd(ctrp, 1);
        if (tid < 32) {
            float4 v = *(const float4*)&sm_ho[tid * 4];
            *(float4*)&g_hist[((size_t)(dir * TT + t) * HH + cg * 32 + tid) * BB + bg * 4] = v;
        }
        __syncthreads();   // protect sm_ho / sm_g / sm_hd reuse
    }
}

// ---------------- kernel C: output projection + log_softmax ----------------
// grid 512 (t), 256 threads. smem: hsm[512][32] + wsm[512][32] + lsm[32][33] + lse[32]
__global__ void proj_kernel(const float* __restrict__ out_W,
                            const float* __restrict__ out_b) {
    extern __shared__ float sm[];
    float* hsm = sm;                       // 512*32
    float* wsm = sm + 512 * 32;            // 512*32
    float* lsm = wsm + 512 * 32;           // 32*33
    float* lse = lsm + 32 * 33;            // 32

    const int t   = blockIdx.x;
    const int tid = threadIdx.x;

    float4* hd = (float4*)hsm;
    const float4* h0 = (const float4*)(g_hist + (size_t)t * HH * BB);
    const float4* h1 = (const float4*)(g_hist + (size_t)(TT + t) * HH * BB);
    #pragma unroll
    for (int i = 0; i < 16; i++) {
        int idx = tid + i * 256;
        hd[idx] = (idx < 2048) ? h0[idx] : h1[idx - 2048];
    }
    float4* wd = (float4*)wsm;
    const float4* w4 = (const float4*)out_W;
    #pragma unroll
    for (int i = 0; i < 16; i++) {
        int idx = tid + i * 256;
        wd[idx] = w4[idx];
    }
    __syncthreads();

    const int b  = tid & 31;
    const int cg = tid >> 5;
    float acc[4];
    #pragma unroll
    for (int jj = 0; jj < 4; jj++) acc[jj] = out_b[cg * 4 + jj];
    #pragma unroll 8
    for (int k = 0; k < 512; k++) {
        float  hv = hsm[k * 32 + b];
        float4 ww = *(const float4*)&wsm[k * 32 + cg * 4];
        acc[0] += hv * ww.x; acc[1] += hv * ww.y; acc[2] += hv * ww.z; acc[3] += hv * ww.w;
    }
    #pragma unroll
    for (int jj = 0; jj < 4; jj++) lsm[b * 33 + cg * 4 + jj] = acc[jj];
    __syncthreads();

    if (tid < 32) {
        float mx = -1e30f;
        #pragma unroll
        for (int c = 0; c < 32; c++) mx = fmaxf(mx, lsm[tid * 33 + c]);
        float ssum = 0.f;
        #pragma unroll
        for (int c = 0; c < 32; c++) ssum += expf(lsm[tid * 33 + c] - mx);
        lse[tid] = mx + logf(ssum);
    }
    __syncthreads();

    float l = lse[b];
    #pragma unroll
    for (int jj = 0; jj < 4; jj++)
        g_logits[(size_t)t * BB * CC + b * CC + cg * 4 + jj] = acc[jj] - l;
}

// ---------------- kernel D: CRF normalizer + gold score (4 warps/batch) ----------------
__global__ void __launch_bounds__(128) crf_kernel(
        const int* __restrict__ seq_len,
        const int* __restrict__ target,
        const float* __restrict__ trans,
        const float* __restrict__ start_trans,
        const float* __restrict__ end_trans,
        float* __restrict__ out) {
    __shared__ float sm_m[2][4][32];
    __shared__ float sm_s[2][4][32];
    __shared__ float sm_r[4];

    const int b   = blockIdx.x;
    const int tid = threadIdx.x;
    const int j   = tid & 31;
    const int w   = tid >> 5;
    const int sl  = seq_len[b];

    float tr8[8];
    #pragma unroll
    for (int ii = 0; ii < 8; ii++) tr8[ii] = trans[(8 * w + ii) * 32 + j];

    float alpha = g_logits[(size_t)b * CC + j] + start_trans[j];

    for (int t = 1; t < sl; t++) {
        float emit = g_logits[(size_t)t * BB * CC + b * CC + j];
        float v[8];
        #pragma unroll
        for (int ii = 0; ii < 8; ii++)
            v[ii] = __shfl_sync(0xffffffffu, alpha, 8 * w + ii) + tr8[ii];
        float mw = fmaxf(fmaxf(fmaxf(v[0], v[1]), fmaxf(v[2], v[3])),
                         fmaxf(fmaxf(v[4], v[5]), fmaxf(v[6], v[7])));
        float sw = 0.f;
        #pragma unroll
        for (int ii = 0; ii < 8; ii++) sw += __expf(v[ii] - mw);

        int par = t & 1;
        sm_m[par][w][j] = mw;
        sm_s[par][w][j] = sw;
        __syncthreads();

        float m0 = sm_m[par][0][j], m1 = sm_m[par][1][j];
        float m2 = sm_m[par][2][j], m3 = sm_m[par][3][j];
        float M = fmaxf(fmaxf(m0, m1), fmaxf(m2, m3));
        float S = sm_s[par][0][j] * __expf(m0 - M) + sm_s[par][1][j] * __expf(m1 - M)
                + sm_s[par][2][j] * __expf(m2 - M) + sm_s[par][3][j] * __expf(m3 - M);
        alpha = M + __logf(S) + emit;
    }

    float vv = alpha + end_trans[j];
    float mx = vv;
    #pragma unroll
    for (int o = 16; o > 0; o >>= 1) mx = fmaxf(mx, __shfl_xor_sync(0xffffffffu, mx, o));
    float se = __expf(vv - mx);
    #pragma unroll
    for (int o = 16; o > 0; o >>= 1) se += __shfl_xor_sync(0xffffffffu, se, o);
    float norm = mx + logf(se);

    float gs = 0.f;
    for (int t = tid; t < sl; t += 128) {
        int tg = target[b * TT + t];
        gs += g_logits[(size_t)t * BB * CC + b * CC + tg];
        if (t >= 1) gs += trans[target[b * TT + t - 1] * 32 + tg];
    }
    #pragma unroll
    for (int o = 16; o > 0; o >>= 1) gs += __shfl_xor_sync(0xffffffffu, gs, o);
    if (j == 0) sm_r[w] = gs;
    __syncthreads();

    if (tid == 0) {
        float g = sm_r[0] + sm_r[1] + sm_r[2] + sm_r[3]
                + start_trans[target[b * TT]] + end_trans[target[b * TT + sl - 1]];
        out[b] = norm - g;
    }
}

// ---------------- launch ----------------
extern "C" void kernel_launch(void* const* d_in, const int* in_sizes, int n_in,
                              void* d_out, int out_size) {
    const int*   chars        = (const int*)d_in[0];
    const int*   bigrams      = (const int*)d_in[1];
    const int*   seq_len      = (const int*)d_in[2];
    const int*   target       = (const int*)d_in[3];
    const float* char_table   = (const float*)d_in[4];
    const float* bigram_table = (const float*)d_in[5];
    const float* Wi_f         = (const float*)d_in[6];
    const float* Wh_f         = (const float*)d_in[7];
    const float* b_f          = (const float*)d_in[8];
    const float* Wi_b         = (const float*)d_in[9];
    const float* Wh_b         = (const float*)d_in[10];
    const float* b_b          = (const float*)d_in[11];
    const float* out_W        = (const float*)d_in[12];
    const float* out_b        = (const float*)d_in[13];
    const float* trans        = (const float*)d_in[14];
    const float* start_trans  = (const float*)d_in[15];
    const float* end_trans    = (const float*)d_in[16];
    float* out = (float*)d_out;

    const int SMEM_A = 32768 + 65536;                                       // 98304
    const int SMEM_S = 131072 + 8192 + 2048 + 6144 + 512;                   // 147968
    const int SMEM_P = (512 * 32 * 2 + 32 * 33 + 32) * (int)sizeof(float);  // 135424

    cudaFuncSetAttribute(wi_gemm_kernel, cudaFuncAttributeMaxDynamicSharedMemorySize, SMEM_A);
    cudaFuncSetAttribute(scan_kernel,    cudaFuncAttributeMaxDynamicSharedMemorySize, SMEM_S);
    cudaFuncSetAttribute(proj_kernel,    cudaFuncAttributeMaxDynamicSharedMemorySize, SMEM_P);

    init_kernel<<<2, 256>>>();

    dim3 ga(TT, 16);
    wi_gemm_kernel<<<ga, 256, SMEM_A>>>(chars, bigrams, char_table, bigram_table,
                                        Wi_f, b_f, Wi_b, b_b);

    scan_kernel<<<128, 128, SMEM_S>>>(Wh_f, Wh_b, seq_len);

    proj_kernel<<<TT, 256, SMEM_P>>>(out_W, out_b);

    crf_kernel<<<BB, 128>>>(seq_len, target, trans, start_trans, end_trans, out);
}

// round 12
// speedup vs baseline: 2.3468x; 1.0880x over previous
#include <cuda_runtime.h>
#include <math.h>
#include <stdint.h>

#define BB   32
#define TT   512
#define HH   256
#define CC   32
#define G4   1024   // 4*H
#define DD   256

typedef unsigned long long ull;

// ---------------- scratch (no allocations allowed) ----------------
// gx layout: [dir][t][b][col]  (col fastest, 1024 per dir)
__device__ float g_gx[(size_t)2 * TT * BB * G4];     // 134 MB
__device__ float g_hist[(size_t)2 * TT * HH * BB];   // [dir][t][n][b]  33 MB
__device__ float g_logits[(size_t)TT * BB * CC];     // [t][b][c]        2 MB
// h exchange slabs per group: [16][parity][256 cols][4 b] duplicated ull
__device__ ull   g_hx[16 * 2048];                    // 256 KB
__device__ int   g_ctr[16 * 32];                     // 1 counter per group, 128B apart

// ---------------- packed fp32x2 helpers ----------------
__device__ __forceinline__ ull ffma2(ull a, ull b, ull c) {
    ull d;
    asm("fma.rn.f32x2 %0, %1, %2, %3;" : "=l"(d) : "l"(a), "l"(b), "l"(c));
    return d;
}
__device__ __forceinline__ ull padd2(ull a, ull b) {
    ull d;
    asm("add.rn.f32x2 %0, %1, %2;" : "=l"(d) : "l"(a), "l"(b));
    return d;
}
__device__ __forceinline__ ull dup2(float x) {
    ull p = (ull)__float_as_uint(x);
    return p | (p << 32);
}
__device__ __forceinline__ float2 unp(ull v) {
    float2 f;
    asm("mov.b64 {%0, %1}, %2;" : "=f"(f.x), "=f"(f.y) : "l"(v));
    return f;
}

__device__ __forceinline__ float sigf(float x)  { return __fdividef(1.f, 1.f + __expf(-x)); }
__device__ __forceinline__ float tanhf_(float x){ return __fdividef(2.f, 1.f + __expf(-2.f * x)) - 1.f; }

// release-add / acquire-load (pair: orders slab stores without per-thread MEMBAR)
__device__ __forceinline__ void red_release_add(int* p, int v) {
    asm volatile("red.release.gpu.global.add.s32 [%0], %1;" :: "l"(p), "r"(v) : "memory");
}
__device__ __forceinline__ int ld_acquire(const int* p) {
    int v;
    asm volatile("ld.acquire.gpu.global.b32 %0, [%1];" : "=r"(v) : "l"(p) : "memory");
    return v;
}

// ---------------- init: zero counters each replay ----------------
__global__ void init_kernel() {
    int i = blockIdx.x * blockDim.x + threadIdx.x;
    if (i < 16 * 32) g_ctr[i] = 0;
}

// ---------------- kernel A: embedding gather + x@Wi + bias (fp32x2) ----------------
// grid (512, 16): x = t, y = dir*8 + colblock(128 cols). 256 threads.
__global__ void __launch_bounds__(256) wi_gemm_kernel(
        const int* __restrict__ chars,
        const int* __restrict__ bigrams,
        const float* __restrict__ char_table,
        const float* __restrict__ bigram_table,
        const float* __restrict__ Wi_f,
        const float* __restrict__ bias_f,
        const float* __restrict__ Wi_b,
        const float* __restrict__ bias_b) {
    extern __shared__ float sm[];
    float* a_sm = sm;                       // 8192 floats = 32KB
    ull*   wd_sm = (ull*)(sm + 8192);       // 8192 ull = 64KB

    const int t   = blockIdx.x;
    const int yid = blockIdx.y;
    const int dir = yid >> 3;
    const int cb  = yid & 7;
    const float* Wi   = dir ? Wi_b  : Wi_f;
    const float* bias = dir ? bias_b : bias_f;

    const int tid = threadIdx.x;

    // gather emb -> a_sm[k][b]
    {
        const int b    = tid & 31;
        const int part = tid >> 5;
        const int ci = chars[b * TT + t];
        const int bi = bigrams[b * TT + t];
        #pragma unroll
        for (int i = 0; i < 8; i++) {
            int k4 = part * 8 + i;
            float4 v;
            if (k4 < 32) v = ((const float4*)char_table)[(size_t)ci * 32 + k4];
            else         v = ((const float4*)bigram_table)[(size_t)bi * 32 + (k4 - 32)];
            a_sm[(k4 * 4 + 0) * 32 + b] = v.x;
            a_sm[(k4 * 4 + 1) * 32 + b] = v.y;
            a_sm[(k4 * 4 + 2) * 32 + b] = v.z;
            a_sm[(k4 * 4 + 3) * 32 + b] = v.w;
        }
    }

    const int cg = tid >> 3;   // cols cg*4 .. cg*4+3
    const int bq = tid & 7;    // batches 4bq .. 4bq+3
    ull acc[8];
    #pragma unroll
    for (int i = 0; i < 8; i++) acc[i] = 0ull;

    const ulonglong2* a2 = (const ulonglong2*)a_sm;

    for (int ch = 0; ch < 4; ch++) {
        const int k0 = ch * 64;
        __syncthreads();
        for (int u = tid; u < 8192; u += 256) {
            int kk  = u >> 7;
            int col = u & 127;
            float wv = Wi[(size_t)(k0 + kk) * G4 + cb * 128 + col];
            wd_sm[u] = dup2(wv);
        }
        __syncthreads();
        #pragma unroll 8
        for (int kk = 0; kk < 64; kk++) {
            ulonglong2 hv = a2[(k0 + kk) * 8 + bq];
            const ull* wr = &wd_sm[kk * 128 + cg * 4];
            #pragma unroll
            for (int c = 0; c < 4; c++) {
                ull wd = wr[c];
                acc[2 * c]     = ffma2(hv.x, wd, acc[2 * c]);
                acc[2 * c + 1] = ffma2(hv.y, wd, acc[2 * c + 1]);
            }
        }
    }

    // transpose in smem, then store as [dir][t][b][col]
    __syncthreads();
    {
        #pragma unroll
        for (int cc = 0; cc < 4; cc++) {
            int col = cg * 4 + cc;
            ull b2 = dup2(bias[cb * 128 + col]);
            float2 v01 = unp(padd2(acc[2 * cc],     b2));
            float2 v23 = unp(padd2(acc[2 * cc + 1], b2));
            a_sm[(bq * 4 + 0) * 129 + col] = v01.x;
            a_sm[(bq * 4 + 1) * 129 + col] = v01.y;
            a_sm[(bq * 4 + 2) * 129 + col] = v23.x;
            a_sm[(bq * 4 + 3) * 129 + col] = v23.y;
        }
    }
    __syncthreads();
    {
        float* outp = g_gx + (size_t)(dir * TT + t) * (32 * 1024) + cb * 128;
        #pragma unroll
        for (int i = 0; i < 4; i++) {
            int idx = tid + i * 256;
            int b = idx >> 5, c4 = idx & 31;
            float4 v;
            v.x = a_sm[b * 129 + c4 * 4 + 0];
            v.y = a_sm[b * 129 + c4 * 4 + 1];
            v.z = a_sm[b * 129 + c4 * 4 + 2];
            v.w = a_sm[b * 129 + c4 * 4 + 3];
            *(float4*)(outp + (size_t)b * 1024 + c4 * 4) = v;
        }
    }
}

// ---------------- kernel B: recurrent scan, 8-CTA groups ----------------
// grid 128 CTAs of 128 threads: CTA = (dir, bg in 0..7, cg in 0..7).
// Group (dir,bg) = 8 CTAs exchanging h of 4 batches via L2 slab + release/acquire counter.
// Truncated to mx = max(seq_len of group); tail of g_hist bulk-filled.
__global__ void __launch_bounds__(128, 1)
scan_kernel(const float* __restrict__ Wh_f,
            const float* __restrict__ Wh_b,
            const int* __restrict__ seq_len) {
    extern __shared__ float sm[];
    float*      sm_wh   = sm;                             // [256][128] f32 = 128KB
    ull*        sm_hd   = (ull*)(sm + 32768);             // [256][4] dup ull = 8KB
    float*      sm_g    = (float*)(sm_hd + 1024);         // [2][4 b][128 l] = 4KB
    ulonglong2* sm_part = (ulonglong2*)(sm_g + 1024);     // [3][32][4] u2 = 6KB
    float*      sm_ho   = (float*)(sm_part + 3 * 32 * 4); // [2][32][4] = 1KB

    const int cta = blockIdx.x;
    const int dir = cta >> 6;
    const int bg  = (cta >> 3) & 7;
    const int cg  = cta & 7;
    const float* Wh = dir ? Wh_b : Wh_f;
    const int tid = threadIdx.x;

    // load Wh slice: sm_wh[k*128 + g*32 + m] = Wh[k][g*256 + cg*32 + m]
    {
        const float4* W4 = (const float4*)Wh;
        float4* d4 = (float4*)sm_wh;
        for (int u = tid; u < 8192; u += 128) {
            int k = u >> 5, l4 = u & 31;
            d4[u] = W4[(k * 1024 + (l4 >> 3) * 256 + cg * 32 + (l4 & 7) * 4) >> 2];
        }
    }
    for (int u = tid; u < 1024; u += 128) sm_hd[u] = 0ull;

    // group max seq len
    const int4 sls = *(const int4*)&seq_len[bg * 4];
    const int mx = max(max(sls.x, sls.y), max(sls.z, sls.w));
    const int nsteps = mx;

    // GEMM mapping
    const int j8 = tid & 15;          // col oct: local cols 8*j8 .. 8*j8+7
    const int bh = (tid >> 4) & 1;    // local batches 2bh, 2bh+1
    const int kh = tid >> 5;          // k quarter
    const int kbase = kh * 64;
    // combine mapping
    const int m  = tid & 31;
    const int bl = tid >> 5;
    const int b_glob = bg * 4 + bl;
    const int sl = seq_len[b_glob];
    const int ncol = cg * 32 + m;

    const int gq  = j8 >> 2;
    const int c0g = gq * 256 + cg * 32 + ((8 * j8) & 31);
    const int b0  = bg * 4 + 2 * bh;

    int* ctrp = &g_ctr[(dir * 8 + bg) * 32];
    ull* slab = &g_hx[(size_t)(dir * 8 + bg) * 2048];

    float c_reg = 0.f, h_prev = 0.f;

    // backward: g_hist is exactly zero for t >= mx (mask never fires, h stays 0)
    if (dir == 1) {
        const int col = tid & 31;
        const int tq  = tid >> 5;
        float4 z = make_float4(0.f, 0.f, 0.f, 0.f);
        for (int tt = mx + tq; tt < TT; tt += 4)
            *(float4*)&g_hist[((size_t)(TT + tt) * HH + cg * 32 + col) * BB + bg * 4] = z;
    }

    // prefetch gx for first computed step
    ulonglong2 q00, q01, q10, q11;
    {
        int t0 = dir ? (mx - 1) : 0;
        if (kh == 0) {
            size_t base = ((size_t)(dir * TT + t0) * 32 + b0) * 1024 + c0g;
            q00 = *(const ulonglong2*)(g_gx + base);
            q01 = *(const ulonglong2*)(g_gx + base + 4);
            q10 = *(const ulonglong2*)(g_gx + base + 1024);
            q11 = *(const ulonglong2*)(g_gx + base + 1028);
        }
    }
    __syncthreads();

    for (int p = 0; p < nsteps; p++) {
        const int t = dir ? (mx - 1 - p) : p;
        const int par = p & 1;

        // acquire previous h (stage slab -> smem)
        if (p > 0) {
            if (tid == 0) {
                while (ld_acquire(ctrp) < 8 * p) { }
            }
            __syncthreads();
            const ulonglong2* src = (const ulonglong2*)(slab + ((p - 1) & 1) * 1024);
            ulonglong2* dst = (ulonglong2*)sm_hd;
            #pragma unroll
            for (int i = 0; i < 4; i++) dst[tid + i * 128] = src[tid + i * 128];
            __syncthreads();
        }

        // ---- GEMM: 8 cols x 2 batches x 64 k per thread ----
        ull a0, a1, a2, a3, a4, a5, a6, a7;
        if (kh == 0) {
            a0 = q00.x; a2 = q00.y; a4 = q01.x; a6 = q01.y;   // batch b0
            a1 = q10.x; a3 = q10.y; a5 = q11.x; a7 = q11.y;   // batch b0+1
        } else {
            a0 = a1 = a2 = a3 = a4 = a5 = a6 = a7 = 0ull;
        }
        #pragma unroll 8
        for (int kk = 0; kk < 64; kk++) {
            int k = kbase + kk;
            ulonglong2 w01 = *(const ulonglong2*)&sm_wh[k * 128 + 8 * j8];
            ulonglong2 w23 = *(const ulonglong2*)&sm_wh[k * 128 + 8 * j8 + 4];
            ulonglong2 hq  = *(const ulonglong2*)&sm_hd[k * 4 + 2 * bh];
            a0 = ffma2(w01.x, hq.x, a0);  a1 = ffma2(w01.x, hq.y, a1);
            a2 = ffma2(w01.y, hq.x, a2);  a3 = ffma2(w01.y, hq.y, a3);
            a4 = ffma2(w23.x, hq.x, a4);  a5 = ffma2(w23.x, hq.y, a5);
            a6 = ffma2(w23.y, hq.x, a6);  a7 = ffma2(w23.y, hq.y, a7);
        }

        // prefetch next step's gx (hidden behind reduction/combine)
        if (kh == 0 && p < nsteps - 1) {
            int tn = dir ? (t - 1) : (t + 1);
            size_t base = ((size_t)(dir * TT + tn) * 32 + b0) * 1024 + c0g;
            q00 = *(const ulonglong2*)(g_gx + base);
            q01 = *(const ulonglong2*)(g_gx + base + 4);
            q10 = *(const ulonglong2*)(g_gx + base + 1024);
            q11 = *(const ulonglong2*)(g_gx + base + 1028);
        }

        // ---- tree reduction over kh ----
        int slot = (bh * 16 + j8) * 4;
        if (kh & 1) {
            ulonglong2* d = &sm_part[(kh >> 1) * 128 + slot];
            d[0] = make_ulonglong2(a0, a1); d[1] = make_ulonglong2(a2, a3);
            d[2] = make_ulonglong2(a4, a5); d[3] = make_ulonglong2(a6, a7);
        }
        __syncthreads();
        if (!(kh & 1)) {
            const ulonglong2* s = &sm_part[(kh >> 1) * 128 + slot];
            ulonglong2 r0 = s[0], r1 = s[1], r2 = s[2], r3 = s[3];
            a0 = padd2(a0, r0.x); a1 = padd2(a1, r0.y);
            a2 = padd2(a2, r1.x); a3 = padd2(a3, r1.y);
            a4 = padd2(a4, r2.x); a5 = padd2(a5, r2.y);
            a6 = padd2(a6, r3.x); a7 = padd2(a7, r3.y);
            if (kh == 2) {
                ulonglong2* d = &sm_part[2 * 128 + slot];
                d[0] = make_ulonglong2(a0, a1); d[1] = make_ulonglong2(a2, a3);
                d[2] = make_ulonglong2(a4, a5); d[3] = make_ulonglong2(a6, a7);
            }
        }
        __syncthreads();
        if (kh == 0) {
            const ulonglong2* s = &sm_part[2 * 128 + slot];
            ulonglong2 r0 = s[0], r1 = s[1], r2 = s[2], r3 = s[3];
            a0 = padd2(a0, r0.x); a1 = padd2(a1, r0.y);
            a2 = padd2(a2, r1.x); a3 = padd2(a3, r1.y);
            a4 = padd2(a4, r2.x); a5 = padd2(a5, r2.y);
            a6 = padd2(a6, r3.x); a7 = padd2(a7, r3.y);
            float2 f0 = unp(a0), f2 = unp(a2), f4 = unp(a4), f6 = unp(a6);
            float2 f1 = unp(a1), f3 = unp(a3), f5 = unp(a5), f7 = unp(a7);
            int lbase = 8 * j8;
            float* gbuf = sm_g + par * 512;
            *(float4*)&gbuf[(2 * bh)     * 128 + lbase]     = make_float4(f0.x, f0.y, f2.x, f2.y);
            *(float4*)&gbuf[(2 * bh)     * 128 + lbase + 4] = make_float4(f4.x, f4.y, f6.x, f6.y);
            *(float4*)&gbuf[(2 * bh + 1) * 128 + lbase]     = make_float4(f1.x, f1.y, f3.x, f3.y);
            *(float4*)&gbuf[(2 * bh + 1) * 128 + lbase + 4] = make_float4(f5.x, f5.y, f7.x, f7.y);
        }
        __syncthreads();

        // ---- combine: thread = (h col m, batch bl) ----
        const float* gbuf = sm_g + par * 512;
        float gi_ = gbuf[bl * 128 +  0 + m];
        float gf_ = gbuf[bl * 128 + 32 + m];
        float gc_ = gbuf[bl * 128 + 64 + m];
        float go_ = gbuf[bl * 128 + 96 + m];
        float c_new = sigf(gf_) * c_reg + sigf(gi_) * tanhf_(gc_);
        float h_new = sigf(go_) * tanhf_(c_new);
        bool  msk = (t < sl);
        if (msk) c_reg = c_new;
        float h_out = msk ? h_new : h_prev;
        h_prev = h_out;

        // publish for peers + stage for coalesced hist store
        if (p < nsteps - 1)
            slab[(p & 1) * 1024 + ncol * 4 + bl] = dup2(h_out);
        sm_ho[par * 128 + m * 4 + bl] = h_out;
        __syncthreads();   // all slab stores + sm_ho visible before release / reads

        if (tid == 0 && p < nsteps - 1) red_release_add(ctrp, 1);
        if (tid < 32) {
            float4 v = *(const float4*)&sm_ho[par * 128 + tid * 4];
            *(float4*)&g_hist[((size_t)(dir * TT + t) * HH + cg * 32 + tid) * BB + bg * 4] = v;
        }
        // no trailing sync: sm_g/sm_ho parity-buffered; sm_hd/sm_part protected by next
        // iteration's post-poll barriers (all reads of this step precede the publish sync)
    }

    // forward: g_hist for t >= mx is the frozen h (per-batch, maintained by mask)
    if (dir == 0) {
        const int lastpar = (nsteps - 1) & 1;
        const int col = tid & 31;
        const int tq  = tid >> 5;
        float4 v = *(const float4*)&sm_ho[lastpar * 128 + col * 4];
        for (int tt = mx + tq; tt < TT; tt += 4)
            *(float4*)&g_hist[((size_t)tt * HH + cg * 32 + col) * BB + bg * 4] = v;
    }
}

// ---------------- kernel C: output projection + log_softmax ----------------
__global__ void proj_kernel(const float* __restrict__ out_W,
                            const float* __restrict__ out_b) {
    extern __shared__ float sm[];
    float* hsm = sm;                       // 512*32
    float* wsm = sm + 512 * 32;            // 512*32
    float* lsm = wsm + 512 * 32;           // 32*33
    float* lse = lsm + 32 * 33;            // 32

    const int t   = blockIdx.x;
    const int tid = threadIdx.x;

    float4* hd = (float4*)hsm;
    const float4* h0 = (const float4*)(g_hist + (size_t)t * HH * BB);
    const float4* h1 = (const float4*)(g_hist + (size_t)(TT + t) * HH * BB);
    #pragma unroll
    for (int i = 0; i < 16; i++) {
        int idx = tid + i * 256;
        hd[idx] = (idx < 2048) ? h0[idx] : h1[idx - 2048];
    }
    float4* wd = (float4*)wsm;
    const float4* w4 = (const float4*)out_W;
    #pragma unroll
    for (int i = 0; i < 16; i++) {
        int idx = tid + i * 256;
        wd[idx] = w4[idx];
    }
    __syncthreads();

    const int b  = tid & 31;
    const int cg = tid >> 5;
    float acc[4];
    #pragma unroll
    for (int jj = 0; jj < 4; jj++) acc[jj] = out_b[cg * 4 + jj];
    #pragma unroll 8
    for (int k = 0; k < 512; k++) {
        float  hv = hsm[k * 32 + b];
        float4 ww = *(const float4*)&wsm[k * 32 + cg * 4];
        acc[0] += hv * ww.x; acc[1] += hv * ww.y; acc[2] += hv * ww.z; acc[3] += hv * ww.w;
    }
    #pragma unroll
    for (int jj = 0; jj < 4; jj++) lsm[b * 33 + cg * 4 + jj] = acc[jj];
    __syncthreads();

    if (tid < 32) {
        float mx = -1e30f;
        #pragma unroll
        for (int c = 0; c < 32; c++) mx = fmaxf(mx, lsm[tid * 33 + c]);
        float ssum = 0.f;
        #pragma unroll
        for (int c = 0; c < 32; c++) ssum += expf(lsm[tid * 33 + c] - mx);
        lse[tid] = mx + logf(ssum);
    }
    __syncthreads();

    float l = lse[b];
    #pragma unroll
    for (int jj = 0; jj < 4; jj++)
        g_logits[(size_t)t * BB * CC + b * CC + cg * 4 + jj] = acc[jj] - l;
}

// ---------------- kernel D: CRF normalizer + gold score (4 warps/batch) ----------------
__global__ void __launch_bounds__(128) crf_kernel(
        const int* __restrict__ seq_len,
        const int* __restrict__ target,
        const float* __restrict__ trans,
        const float* __restrict__ start_trans,
        const float* __restrict__ end_trans,
        float* __restrict__ out) {
    __shared__ float sm_m[2][4][32];
    __shared__ float sm_s[2][4][32];
    __shared__ float sm_r[4];

    const int b   = blockIdx.x;
    const int tid = threadIdx.x;
    const int j   = tid & 31;
    const int w   = tid >> 5;
    const int sl  = seq_len[b];

    float tr8[8];
    #pragma unroll
    for (int ii = 0; ii < 8; ii++) tr8[ii] = trans[(8 * w + ii) * 32 + j];

    float alpha = g_logits[(size_t)b * CC + j] + start_trans[j];

    for (int t = 1; t < sl; t++) {
        float emit = g_logits[(size_t)t * BB * CC + b * CC + j];
        float v[8];
        #pragma unroll
        for (int ii = 0; ii < 8; ii++)
            v[ii] = __shfl_sync(0xffffffffu, alpha, 8 * w + ii) + tr8[ii];
        float mw = fmaxf(fmaxf(fmaxf(v[0], v[1]), fmaxf(v[2], v[3])),
                         fmaxf(fmaxf(v[4], v[5]), fmaxf(v[6], v[7])));
        float sw = 0.f;
        #pragma unroll
        for (int ii = 0; ii < 8; ii++) sw += __expf(v[ii] - mw);

        int par = t & 1;
        sm_m[par][w][j] = mw;
        sm_s[par][w][j] = sw;
        __syncthreads();

        float m0 = sm_m[par][0][j], m1 = sm_m[par][1][j];
        float m2 = sm_m[par][2][j], m3 = sm_m[par][3][j];
        float M = fmaxf(fmaxf(m0, m1), fmaxf(m2, m3));
        float S = sm_s[par][0][j] * __expf(m0 - M) + sm_s[par][1][j] * __expf(m1 - M)
                + sm_s[par][2][j] * __expf(m2 - M) + sm_s[par][3][j] * __expf(m3 - M);
        alpha = M + __logf(S) + emit;
    }

    float vv = alpha + end_trans[j];
    float mx = vv;
    #pragma unroll
    for (int o = 16; o > 0; o >>= 1) mx = fmaxf(mx, __shfl_xor_sync(0xffffffffu, mx, o));
    float se = __expf(vv - mx);
    #pragma unroll
    for (int o = 16; o > 0; o >>= 1) se += __shfl_xor_sync(0xffffffffu, se, o);
    float norm = mx + logf(se);

    float gs = 0.f;
    for (int t = tid; t < sl; t += 128) {
        int tg = target[b * TT + t];
        gs += g_logits[(size_t)t * BB * CC + b * CC + tg];
        if (t >= 1) gs += trans[target[b * TT + t - 1] * 32 + tg];
    }
    #pragma unroll
    for (int o = 16; o > 0; o >>= 1) gs += __shfl_xor_sync(0xffffffffu, gs, o);
    if (j == 0) sm_r[w] = gs;
    __syncthreads();

    if (tid == 0) {
        float g = sm_r[0] + sm_r[1] + sm_r[2] + sm_r[3]
                + start_trans[target[b * TT]] + end_trans[target[b * TT + sl - 1]];
        out[b] = norm - g;
    }
}

// ---------------- launch ----------------
extern "C" void kernel_launch(void* const* d_in, const int* in_sizes, int n_in,
                              void* d_out, int out_size) {
    const int*   chars        = (const int*)d_in[0];
    const int*   bigrams      = (const int*)d_in[1];
    const int*   seq_len      = (const int*)d_in[2];
    const int*   target       = (const int*)d_in[3];
    const float* char_table   = (const float*)d_in[4];
    const float* bigram_table = (const float*)d_in[5];
    const float* Wi_f         = (const float*)d_in[6];
    const float* Wh_f         = (const float*)d_in[7];
    const float* b_f          = (const float*)d_in[8];
    const float* Wi_b         = (const float*)d_in[9];
    const float* Wh_b         = (const float*)d_in[10];
    const float* b_b          = (const float*)d_in[11];
    const float* out_W        = (const float*)d_in[12];
    const float* out_b        = (const float*)d_in[13];
    const float* trans        = (const float*)d_in[14];
    const float* start_trans  = (const float*)d_in[15];
    const float* end_trans    = (const float*)d_in[16];
    float* out = (float*)d_out;

    const int SMEM_A = 32768 + 65536;                                       // 98304
    const int SMEM_S = 131072 + 8192 + 4096 + 6144 + 1024;                  // 150528
    const int SMEM_P = (512 * 32 * 2 + 32 * 33 + 32) * (int)sizeof(float);  // 135424

    cudaFuncSetAttribute(wi_gemm_kernel, cudaFuncAttributeMaxDynamicSharedMemorySize, SMEM_A);
    cudaFuncSetAttribute(scan_kernel,    cudaFuncAttributeMaxDynamicSharedMemorySize, SMEM_S);
    cudaFuncSetAttribute(proj_kernel,    cudaFuncAttributeMaxDynamicSharedMemorySize, SMEM_P);

    init_kernel<<<2, 256>>>();

    dim3 ga(TT, 16);
    wi_gemm_kernel<<<ga, 256, SMEM_A>>>(chars, bigrams, char_table, bigram_table,
                                        Wi_f, b_f, Wi_b, b_b);

    scan_kernel<<<128, 128, SMEM_S>>>(Wh_f, Wh_b, seq_len);

    proj_kernel<<<TT, 256, SMEM_P>>>(out_W, out_b);

    crf_kernel<<<BB, 128>>>(seq_len, target, trans, start_trans, end_trans, out);
}

// round 13
// speedup vs baseline: 2.3956x; 1.0208x over previous
#include <cuda_runtime.h>
#include <math.h>
#include <stdint.h>

#define BB   32
#define TT   512
#define HH   256
#define CC   32
#define G4   1024   // 4*H
#define DD   256

typedef unsigned long long ull;

// ---------------- scratch (no allocations allowed) ----------------
// gx layout: [dir][t][b][col]  (col fastest, 1024 per dir)
__device__ float g_gx[(size_t)2 * TT * BB * G4];     // 134 MB
__device__ float g_hist[(size_t)2 * TT * HH * BB];   // [dir][t][n][b]  33 MB
__device__ float g_logits[(size_t)TT * BB * CC];     // [t][b][c]        2 MB
// h exchange slabs per group: [16][parity][256 cols][4 b] duplicated ull
__device__ ull   g_hx[16 * 2048];                    // 256 KB
__device__ int   g_ctr[16 * 32];                     // 1 counter per group, 128B apart

// ---------------- packed fp32x2 helpers ----------------
__device__ __forceinline__ ull ffma2(ull a, ull b, ull c) {
    ull d;
    asm("fma.rn.f32x2 %0, %1, %2, %3;" : "=l"(d) : "l"(a), "l"(b), "l"(c));
    return d;
}
__device__ __forceinline__ ull padd2(ull a, ull b) {
    ull d;
    asm("add.rn.f32x2 %0, %1, %2;" : "=l"(d) : "l"(a), "l"(b));
    return d;
}
__device__ __forceinline__ ull dup2(float x) {
    ull p = (ull)__float_as_uint(x);
    return p | (p << 32);
}
__device__ __forceinline__ float2 unp(ull v) {
    float2 f;
    asm("mov.b64 {%0, %1}, %2;" : "=f"(f.x), "=f"(f.y) : "l"(v));
    return f;
}

__device__ __forceinline__ float sigf(float x)  { return __fdividef(1.f, 1.f + __expf(-x)); }
__device__ __forceinline__ float tanhf_(float x){ return __fdividef(2.f, 1.f + __expf(-2.f * x)) - 1.f; }

// release-add / acquire-load pair
__device__ __forceinline__ void red_release_add(int* p, int v) {
    asm volatile("red.release.gpu.global.add.s32 [%0], %1;" :: "l"(p), "r"(v) : "memory");
}
__device__ __forceinline__ int ld_acquire(const int* p) {
    int v;
    asm volatile("ld.acquire.gpu.global.b32 %0, [%1];" : "=r"(v) : "l"(p) : "memory");
    return v;
}

// ---------------- init: zero counters each replay ----------------
__global__ void init_kernel() {
    int i = blockIdx.x * blockDim.x + threadIdx.x;
    if (i < 16 * 32) g_ctr[i] = 0;
}

// ---------------- kernel A: embedding gather + x@Wi + bias (fp32x2) ----------------
// grid (512, 16): x = t, y = dir*8 + colblock(128 cols). 256 threads.
__global__ void __launch_bounds__(256) wi_gemm_kernel(
        const int* __restrict__ chars,
        const int* __restrict__ bigrams,
        const float* __restrict__ char_table,
        const float* __restrict__ bigram_table,
        const float* __restrict__ Wi_f,
        const float* __restrict__ bias_f,
        const float* __restrict__ Wi_b,
        const float* __restrict__ bias_b) {
    extern __shared__ float sm[];
    float* a_sm = sm;                       // 8192 floats = 32KB
    ull*   wd_sm = (ull*)(sm + 8192);       // 8192 ull = 64KB

    const int t   = blockIdx.x;
    const int yid = blockIdx.y;
    const int dir = yid >> 3;
    const int cb  = yid & 7;
    const float* Wi   = dir ? Wi_b  : Wi_f;
    const float* bias = dir ? bias_b : bias_f;

    const int tid = threadIdx.x;

    // gather emb -> a_sm[k][b]
    {
        const int b    = tid & 31;
        const int part = tid >> 5;
        const int ci = chars[b * TT + t];
        const int bi = bigrams[b * TT + t];
        #pragma unroll
        for (int i = 0; i < 8; i++) {
            int k4 = part * 8 + i;
            float4 v;
            if (k4 < 32) v = ((const float4*)char_table)[(size_t)ci * 32 + k4];
            else         v = ((const float4*)bigram_table)[(size_t)bi * 32 + (k4 - 32)];
            a_sm[(k4 * 4 + 0) * 32 + b] = v.x;
            a_sm[(k4 * 4 + 1) * 32 + b] = v.y;
            a_sm[(k4 * 4 + 2) * 32 + b] = v.z;
            a_sm[(k4 * 4 + 3) * 32 + b] = v.w;
        }
    }

    const int cg = tid >> 3;   // cols cg*4 .. cg*4+3
    const int bq = tid & 7;    // batches 4bq .. 4bq+3
    ull acc[8];
    #pragma unroll
    for (int i = 0; i < 8; i++) acc[i] = 0ull;

    const ulonglong2* a2 = (const ulonglong2*)a_sm;

    for (int ch = 0; ch < 4; ch++) {
        const int k0 = ch * 64;
        __syncthreads();
        for (int u = tid; u < 8192; u += 256) {
            int kk  = u >> 7;
            int col = u & 127;
            float wv = Wi[(size_t)(k0 + kk) * G4 + cb * 128 + col];
            wd_sm[u] = dup2(wv);
        }
        __syncthreads();
        #pragma unroll 8
        for (int kk = 0; kk < 64; kk++) {
            ulonglong2 hv = a2[(k0 + kk) * 8 + bq];
            const ull* wr = &wd_sm[kk * 128 + cg * 4];
            #pragma unroll
            for (int c = 0; c < 4; c++) {
                ull wd = wr[c];
                acc[2 * c]     = ffma2(hv.x, wd, acc[2 * c]);
                acc[2 * c + 1] = ffma2(hv.y, wd, acc[2 * c + 1]);
            }
        }
    }

    // transpose in smem, then store as [dir][t][b][col]
    __syncthreads();
    {
        #pragma unroll
        for (int cc = 0; cc < 4; cc++) {
            int col = cg * 4 + cc;
            ull b2 = dup2(bias[cb * 128 + col]);
            float2 v01 = unp(padd2(acc[2 * cc],     b2));
            float2 v23 = unp(padd2(acc[2 * cc + 1], b2));
            a_sm[(bq * 4 + 0) * 129 + col] = v01.x;
            a_sm[(bq * 4 + 1) * 129 + col] = v01.y;
            a_sm[(bq * 4 + 2) * 129 + col] = v23.x;
            a_sm[(bq * 4 + 3) * 129 + col] = v23.y;
        }
    }
    __syncthreads();
    {
        float* outp = g_gx + (size_t)(dir * TT + t) * (32 * 1024) + cb * 128;
        #pragma unroll
        for (int i = 0; i < 4; i++) {
            int idx = tid + i * 256;
            int b = idx >> 5, c4 = idx & 31;
            float4 v;
            v.x = a_sm[b * 129 + c4 * 4 + 0];
            v.y = a_sm[b * 129 + c4 * 4 + 1];
            v.z = a_sm[b * 129 + c4 * 4 + 2];
            v.w = a_sm[b * 129 + c4 * 4 + 3];
            *(float4*)(outp + (size_t)b * 1024 + c4 * 4) = v;
        }
    }
}

// ---------------- kernel B: recurrent scan, 8-CTA groups, short handoff ----------------
// grid 128 CTAs of 128 threads: CTA = (dir, bg in 0..7, cg in 0..7).
// Per step: all-thread acquire-poll -> per-warp stage (syncwarp) -> GEMM ->
// flat reduction (2 barriers) -> combine+publish (1 barrier) -> release.
__global__ void __launch_bounds__(128, 1)
scan_kernel(const float* __restrict__ Wh_f,
            const float* __restrict__ Wh_b,
            const int* __restrict__ seq_len) {
    extern __shared__ float sm[];
    float*      sm_wh   = sm;                             // [256][128] f32 = 128KB
    ull*        sm_hd   = (ull*)(sm + 32768);             // [256][4] dup ull = 8KB
    float*      sm_g    = (float*)(sm_hd + 1024);         // [2][4 b][128 l] = 4KB
    ulonglong2* sm_part = (ulonglong2*)(sm_g + 1024);     // [3][32][4] u2 = 6KB
    float*      sm_ho   = (float*)(sm_part + 3 * 32 * 4); // [2][32][4] = 1KB

    const int cta = blockIdx.x;
    const int dir = cta >> 6;
    const int bg  = (cta >> 3) & 7;
    const int cg  = cta & 7;
    const float* Wh = dir ? Wh_b : Wh_f;
    const int tid = threadIdx.x;

    // load Wh slice: sm_wh[k*128 + g*32 + m] = Wh[k][g*256 + cg*32 + m]
    {
        const float4* W4 = (const float4*)Wh;
        float4* d4 = (float4*)sm_wh;
        for (int u = tid; u < 8192; u += 128) {
            int k = u >> 5, l4 = u & 31;
            d4[u] = W4[(k * 1024 + (l4 >> 3) * 256 + cg * 32 + (l4 & 7) * 4) >> 2];
        }
    }
    for (int u = tid; u < 1024; u += 128) sm_hd[u] = 0ull;

    // group max seq len
    const int4 sls = *(const int4*)&seq_len[bg * 4];
    const int mx = max(max(sls.x, sls.y), max(sls.z, sls.w));
    const int nsteps = mx;

    // GEMM mapping
    const int j8 = tid & 15;          // col oct: local cols 8*j8 .. 8*j8+7
    const int bh = (tid >> 4) & 1;    // local batches 2bh, 2bh+1
    const int kh = tid >> 5;          // k quarter (== warp id)
    const int kbase = kh * 64;
    const int lane = tid & 31;
    // combine mapping
    const int m  = tid & 31;
    const int bl = tid >> 5;
    const int b_glob = bg * 4 + bl;
    const int sl = seq_len[b_glob];
    const int ncol = cg * 32 + m;

    const int gq  = j8 >> 2;
    const int c0g = gq * 256 + cg * 32 + ((8 * j8) & 31);
    const int b0  = bg * 4 + 2 * bh;

    int* ctrp = &g_ctr[(dir * 8 + bg) * 32];
    ull* slab = &g_hx[(size_t)(dir * 8 + bg) * 2048];

    float c_reg = 0.f, h_prev = 0.f;

    // backward: g_hist is exactly zero for t >= mx (mask never fires, h stays 0)
    if (dir == 1) {
        const int col = tid & 31;
        const int tq  = tid >> 5;
        float4 z = make_float4(0.f, 0.f, 0.f, 0.f);
        for (int tt = mx + tq; tt < TT; tt += 4)
            *(float4*)&g_hist[((size_t)(TT + tt) * HH + cg * 32 + col) * BB + bg * 4] = z;
    }

    // prefetch gx for first computed step
    ulonglong2 q00, q01, q10, q11;
    {
        int t0 = dir ? (mx - 1) : 0;
        if (kh == 0) {
            size_t base = ((size_t)(dir * TT + t0) * 32 + b0) * 1024 + c0g;
            q00 = *(const ulonglong2*)(g_gx + base);
            q01 = *(const ulonglong2*)(g_gx + base + 4);
            q10 = *(const ulonglong2*)(g_gx + base + 1024);
            q11 = *(const ulonglong2*)(g_gx + base + 1028);
        }
    }
    __syncthreads();

    for (int p = 0; p < nsteps; p++) {
        const int t = dir ? (mx - 1 - p) : p;
        const int par = p & 1;

        // acquire previous h: all threads poll (broadcast), then each WARP stages
        // only its own k-slice; warps proceed to GEMM independently.
        if (p > 0) {
            while (ld_acquire(ctrp) < 8 * p) { }
            const ulonglong2* src = (const ulonglong2*)(slab + ((p - 1) & 1) * 1024);
            ulonglong2* dst = (ulonglong2*)sm_hd;
            #pragma unroll
            for (int i = 0; i < 4; i++) {
                int idx = kh * 128 + i * 32 + lane;   // warp-private slice
                dst[idx] = src[idx];
            }
            __syncwarp();
        }

        // ---- GEMM: 8 cols x 2 batches x 64 k per thread ----
        ull a0, a1, a2, a3, a4, a5, a6, a7;
        if (kh == 0) {
            a0 = q00.x; a2 = q00.y; a4 = q01.x; a6 = q01.y;   // batch b0
            a1 = q10.x; a3 = q10.y; a5 = q11.x; a7 = q11.y;   // batch b0+1
        } else {
            a0 = a1 = a2 = a3 = a4 = a5 = a6 = a7 = 0ull;
        }
        #pragma unroll 8
        for (int kk = 0; kk < 64; kk++) {
            int k = kbase + kk;
            ulonglong2 w01 = *(const ulonglong2*)&sm_wh[k * 128 + 8 * j8];
            ulonglong2 w23 = *(const ulonglong2*)&sm_wh[k * 128 + 8 * j8 + 4];
            ulonglong2 hq  = *(const ulonglong2*)&sm_hd[k * 4 + 2 * bh];
            a0 = ffma2(w01.x, hq.x, a0);  a1 = ffma2(w01.x, hq.y, a1);
            a2 = ffma2(w01.y, hq.x, a2);  a3 = ffma2(w01.y, hq.y, a3);
            a4 = ffma2(w23.x, hq.x, a4);  a5 = ffma2(w23.x, hq.y, a5);
            a6 = ffma2(w23.y, hq.x, a6);  a7 = ffma2(w23.y, hq.y, a7);
        }

        // prefetch next step's gx (hidden behind reduction/combine)
        if (kh == 0 && p < nsteps - 1) {
            int tn = dir ? (t - 1) : (t + 1);
            size_t base = ((size_t)(dir * TT + tn) * 32 + b0) * 1024 + c0g;
            q00 = *(const ulonglong2*)(g_gx + base);
            q01 = *(const ulonglong2*)(g_gx + base + 4);
            q10 = *(const ulonglong2*)(g_gx + base + 1024);
            q11 = *(const ulonglong2*)(g_gx + base + 1028);
        }

        // ---- flat reduction: kh=1,2,3 write partials, kh=0 accumulates ----
        const int slot = (bh * 16 + j8) * 4;
        if (kh != 0) {
            ulonglong2* d = &sm_part[(kh - 1) * 128 + slot];
            d[0] = make_ulonglong2(a0, a1); d[1] = make_ulonglong2(a2, a3);
            d[2] = make_ulonglong2(a4, a5); d[3] = make_ulonglong2(a6, a7);
        }
        __syncthreads();   // A: partials visible
        if (kh == 0) {
            const ulonglong2* s0 = &sm_part[0 * 128 + slot];
            const ulonglong2* s1 = &sm_part[1 * 128 + slot];
            const ulonglong2* s2 = &sm_part[2 * 128 + slot];
            ulonglong2 p00 = s0[0], p01 = s0[1], p02 = s0[2], p03 = s0[3];
            ulonglong2 p10 = s1[0], p11 = s1[1], p12 = s1[2], p13 = s1[3];
            ulonglong2 p20 = s2[0], p21 = s2[1], p22 = s2[2], p23 = s2[3];
            a0 = padd2(padd2(a0, p00.x), padd2(p10.x, p20.x));
            a1 = padd2(padd2(a1, p00.y), padd2(p10.y, p20.y));
            a2 = padd2(padd2(a2, p01.x), padd2(p11.x, p21.x));
            a3 = padd2(padd2(a3, p01.y), padd2(p11.y, p21.y));
            a4 = padd2(padd2(a4, p02.x), padd2(p12.x, p22.x));
            a5 = padd2(padd2(a5, p02.y), padd2(p12.y, p22.y));
            a6 = padd2(padd2(a6, p03.x), padd2(p13.x, p23.x));
            a7 = padd2(padd2(a7, p03.y), padd2(p13.y, p23.y));
            float2 f0 = unp(a0), f2 = unp(a2), f4 = unp(a4), f6 = unp(a6);
            float2 f1 = unp(a1), f3 = unp(a3), f5 = unp(a5), f7 = unp(a7);
            int lbase = 8 * j8;
            float* gbuf = sm_g + par * 512;
            *(float4*)&gbuf[(2 * bh)     * 128 + lbase]     = make_float4(f0.x, f0.y, f2.x, f2.y);
            *(float4*)&gbuf[(2 * bh)     * 128 + lbase + 4] = make_float4(f4.x, f4.y, f6.x, f6.y);
            *(float4*)&gbuf[(2 * bh + 1) * 128 + lbase]     = make_float4(f1.x, f1.y, f3.x, f3.y);
            *(float4*)&gbuf[(2 * bh + 1) * 128 + lbase + 4] = make_float4(f5.x, f5.y, f7.x, f7.y);
        }
        __syncthreads();   // B: gates visible

        // ---- combine: thread = (h col m, batch bl) ----
        const float* gbuf = sm_g + par * 512;
        float gi_ = gbuf[bl * 128 +  0 + m];
        float gf_ = gbuf[bl * 128 + 32 + m];
        float gc_ = gbuf[bl * 128 + 64 + m];
        float go_ = gbuf[bl * 128 + 96 + m];
        float c_new = sigf(gf_) * c_reg + sigf(gi_) * tanhf_(gc_);
        float h_new = sigf(go_) * tanhf_(c_new);
        bool  msk = (t < sl);
        if (msk) c_reg = c_new;
        float h_out = msk ? h_new : h_prev;
        h_prev = h_out;

        // publish for peers + stage for coalesced hist store
        if (p < nsteps - 1)
            slab[(p & 1) * 1024 + ncol * 4 + bl] = dup2(h_out);
        sm_ho[par * 128 + m * 4 + bl] = h_out;
        __syncthreads();   // C: slab stores ordered before release; sm_ho visible

        if (tid == 0 && p < nsteps - 1) red_release_add(ctrp, 1);
        if (tid < 32) {
            float4 v = *(const float4*)&sm_ho[par * 128 + tid * 4];
            *(float4*)&g_hist[((size_t)(dir * TT + t) * HH + cg * 32 + tid) * BB + bg * 4] = v;
        }
        // sm_g/sm_ho parity-buffered; sm_hd warp-private; sm_part reused only
        // after next iteration's barrier A — no trailing sync needed.
    }

    // forward: g_hist for t >= mx is the frozen h (per-batch, maintained by mask)
    if (dir == 0) {
        const int lastpar = (nsteps - 1) & 1;
        const int col = tid & 31;
        const int tq  = tid >> 5;
        float4 v = *(const float4*)&sm_ho[lastpar * 128 + col * 4];
        for (int tt = mx + tq; tt < TT; tt += 4)
            *(float4*)&g_hist[((size_t)tt * HH + cg * 32 + col) * BB + bg * 4] = v;
    }
}

// ---------------- kernel C: output projection + log_softmax ----------------
__global__ void proj_kernel(const float* __restrict__ out_W,
                            const float* __restrict__ out_b) {
    extern __shared__ float sm[];
    float* hsm = sm;                       // 512*32
    float* wsm = sm + 512 * 32;            // 512*32
    float* lsm = wsm + 512 * 32;           // 32*33
    float* lse = lsm + 32 * 33;            // 32

    const int t   = blockIdx.x;
    const int tid = threadIdx.x;

    float4* hd = (float4*)hsm;
    const float4* h0 = (const float4*)(g_hist + (size_t)t * HH * BB);
    const float4* h1 = (const float4*)(g_hist + (size_t)(TT + t) * HH * BB);
    #pragma unroll
    for (int i = 0; i < 16; i++) {
        int idx = tid + i * 256;
        hd[idx] = (idx < 2048) ? h0[idx] : h1[idx - 2048];
    }
    float4* wd = (float4*)wsm;
    const float4* w4 = (const float4*)out_W;
    #pragma unroll
    for (int i = 0; i < 16; i++) {
        int idx = tid + i * 256;
        wd[idx] = w4[idx];
    }
    __syncthreads();

    const int b  = tid & 31;
    const int cg = tid >> 5;
    float acc[4];
    #pragma unroll
    for (int jj = 0; jj < 4; jj++) acc[jj] = out_b[cg * 4 + jj];
    #pragma unroll 8
    for (int k = 0; k < 512; k++) {
        float  hv = hsm[k * 32 + b];
        float4 ww = *(const float4*)&wsm[k * 32 + cg * 4];
        acc[0] += hv * ww.x; acc[1] += hv * ww.y; acc[2] += hv * ww.z; acc[3] += hv * ww.w;
    }
    #pragma unroll
    for (int jj = 0; jj < 4; jj++) lsm[b * 33 + cg * 4 + jj] = acc[jj];
    __syncthreads();

    if (tid < 32) {
        float mx = -1e30f;
        #pragma unroll
        for (int c = 0; c < 32; c++) mx = fmaxf(mx, lsm[tid * 33 + c]);
        float ssum = 0.f;
        #pragma unroll
        for (int c = 0; c < 32; c++) ssum += expf(lsm[tid * 33 + c] - mx);
        lse[tid] = mx + logf(ssum);
    }
    __syncthreads();

    float l = lse[b];
    #pragma unroll
    for (int jj = 0; jj < 4; jj++)
        g_logits[(size_t)t * BB * CC + b * CC + cg * 4 + jj] = acc[jj] - l;
}

// ---------------- kernel D: CRF normalizer + gold score (4 warps/batch) ----------------
__global__ void __launch_bounds__(128) crf_kernel(
        const int* __restrict__ seq_len,
        const int* __restrict__ target,
        const float* __restrict__ trans,
        const float* __restrict__ start_trans,
        const float* __restrict__ end_trans,
        float* __restrict__ out) {
    __shared__ float sm_m[2][4][32];
    __shared__ float sm_s[2][4][32];
    __shared__ float sm_r[4];

    const int b   = blockIdx.x;
    const int tid = threadIdx.x;
    const int j   = tid & 31;
    const int w   = tid >> 5;
    const int sl  = seq_len[b];

    float tr8[8];
    #pragma unroll
    for (int ii = 0; ii < 8; ii++) tr8[ii] = trans[(8 * w + ii) * 32 + j];

    float alpha = g_logits[(size_t)b * CC + j] + start_trans[j];

    for (int t = 1; t < sl; t++) {
        float emit = g_logits[(size_t)t * BB * CC + b * CC + j];
        float v[8];
        #pragma unroll
        for (int ii = 0; ii < 8; ii++)
            v[ii] = __shfl_sync(0xffffffffu, alpha, 8 * w + ii) + tr8[ii];
        float mw = fmaxf(fmaxf(fmaxf(v[0], v[1]), fmaxf(v[2], v[3])),
                         fmaxf(fmaxf(v[4], v[5]), fmaxf(v[6], v[7])));
        float sw = 0.f;
        #pragma unroll
        for (int ii = 0; ii < 8; ii++) sw += __expf(v[ii] - mw);

        int par = t & 1;
        sm_m[par][w][j] = mw;
        sm_s[par][w][j] = sw;
        __syncthreads();

        float m0 = sm_m[par][0][j], m1 = sm_m[par][1][j];
        float m2 = sm_m[par][2][j], m3 = sm_m[par][3][j];
        float M = fmaxf(fmaxf(m0, m1), fmaxf(m2, m3));
        float S = sm_s[par][0][j] * __expf(m0 - M) + sm_s[par][1][j] * __expf(m1 - M)
                + sm_s[par][2][j] * __expf(m2 - M) + sm_s[par][3][j] * __expf(m3 - M);
        alpha = M + __logf(S) + emit;
    }

    float vv = alpha + end_trans[j];
    float mx = vv;
    #pragma unroll
    for (int o = 16; o > 0; o >>= 1) mx = fmaxf(mx, __shfl_xor_sync(0xffffffffu, mx, o));
    float se = __expf(vv - mx);
    #pragma unroll
    for (int o = 16; o > 0; o >>= 1) se += __shfl_xor_sync(0xffffffffu, se, o);
    float norm = mx + logf(se);

    float gs = 0.f;
    for (int t = tid; t < sl; t += 128) {
        int tg = target[b * TT + t];
        gs += g_logits[(size_t)t * BB * CC + b * CC + tg];
        if (t >= 1) gs += trans[target[b * TT + t - 1] * 32 + tg];
    }
    #pragma unroll
    for (int o = 16; o > 0; o >>= 1) gs += __shfl_xor_sync(0xffffffffu, gs, o);
    if (j == 0) sm_r[w] = gs;
    __syncthreads();

    if (tid == 0) {
        float g = sm_r[0] + sm_r[1] + sm_r[2] + sm_r[3]
                + start_trans[target[b * TT]] + end_trans[target[b * TT + sl - 1]];
        out[b] = norm - g;
    }
}

// ---------------- launch ----------------
extern "C" void kernel_launch(void* const* d_in, const int* in_sizes, int n_in,
                              void* d_out, int out_size) {
    const int*   chars        = (const int*)d_in[0];
    const int*   bigrams      = (const int*)d_in[1];
    const int*   seq_len      = (const int*)d_in[2];
    const int*   target       = (const int*)d_in[3];
    const float* char_table   = (const float*)d_in[4];
    const float* bigram_table = (const float*)d_in[5];
    const float* Wi_f         = (const float*)d_in[6];
    const float* Wh_f         = (const float*)d_in[7];
    const float* b_f          = (const float*)d_in[8];
    const float* Wi_b         = (const float*)d_in[9];
    const float* Wh_b         = (const float*)d_in[10];
    const float* b_b          = (const float*)d_in[11];
    const float* out_W        = (const float*)d_in[12];
    const float* out_b        = (const float*)d_in[13];
    const float* trans        = (const float*)d_in[14];
    const float* start_trans  = (const float*)d_in[15];
    const float* end_trans    = (const float*)d_in[16];
    float* out = (float*)d_out;

    const int SMEM_A = 32768 + 65536;                                       // 98304
    const int SMEM_S = 131072 + 8192 + 4096 + 6144 + 1024;                  // 150528
    const int SMEM_P = (512 * 32 * 2 + 32 * 33 + 32) * (int)sizeof(float);  // 135424

    cudaFuncSetAttribute(wi_gemm_kernel, cudaFuncAttributeMaxDynamicSharedMemorySize, SMEM_A);
    cudaFuncSetAttribute(scan_kernel,    cudaFuncAttributeMaxDynamicSharedMemorySize, SMEM_S);
    cudaFuncSetAttribute(proj_kernel,    cudaFuncAttributeMaxDynamicSharedMemorySize, SMEM_P);

    init_kernel<<<2, 256>>>();

    dim3 ga(TT, 16);
    wi_gemm_kernel<<<ga, 256, SMEM_A>>>(chars, bigrams, char_table, bigram_table,
                                        Wi_f, b_f, Wi_b, b_b);

    scan_kernel<<<128, 128, SMEM_S>>>(Wh_f, Wh_b, seq_len);

    proj_kernel<<<TT, 256, SMEM_P>>>(out_W, out_b);

    crf_kernel<<<BB, 128>>>(seq_len, target, trans, start_trans, end_trans, out);
}